// round 3
// baseline (speedup 1.0000x reference)
#include <cuda_runtime.h>
#include <math.h>

// ----- problem dims -----
#define B_    32
#define T_    100
#define NN_   32
#define F_    8
#define D_    256
#define LH    512
#define G4    2048      // 4*LH
#define ROWS  3200      // B_*T_  (row = t*32 + b)
#define NBLK  128       // persistent LSTM grid

typedef unsigned long long ull;

// ----- device scratch -----
__device__ float d_G  [ROWS * D_];
__device__ float d_V  [ROWS * D_];
__device__ float d_ATT[ROWS * D_];
__device__ float d_X  [ROWS * G4];
__device__ float d_bihh[G4];
// hidden state, float4-grouped k-major: element (j,b) at (j>>2)*128 + b*4 + (j&3)
__device__ float d_hbuf[2][B_ * LH];
__device__ float d_L  [ROWS * LH];
__device__ float d_H1 [ROWS * D_];
__device__ int   d_bar;

__device__ __forceinline__ void ffma2(ull& d, ull a, ull b) {
    asm("fma.rn.f32x2 %0, %1, %2, %0;" : "+l"(d) : "l"(a), "l"(b));
}
__device__ __forceinline__ ull dup2(float v) {
    float2 f = make_float2(v, v);
    return *(ull*)&f;
}

// ======================================================================
__global__ void k_zero() {
    int i = blockIdx.x * blockDim.x + threadIdx.x;
    if (i < B_ * LH) d_hbuf[0][i] = 0.0f;
    if (i == 0) d_bar = 0;
}

__global__ void k_bihh(const float* __restrict__ bih, const float* __restrict__ bhh) {
    int i = blockIdx.x * blockDim.x + threadIdx.x;
    if (i < G4) d_bihh[i] = bih[i] + bhh[i];
}

// ======================================================================
// G[row,d] = relu( (mean_n traj[b,t,n,:]) @ gcn_w + gcn_b )
// ======================================================================
__global__ void k_G(const float* __restrict__ traj,
                    const float* __restrict__ gw,
                    const float* __restrict__ gb) {
    int row = blockIdx.x;
    int t = row >> 5, b = row & 31;
    __shared__ float s[NN_ * F_];
    __shared__ float m[F_];
    int tid = threadIdx.x;
    const float* p = traj + (size_t)((b * T_ + t) * NN_) * F_;
    s[tid] = p[tid];
    __syncthreads();
    if (tid < F_) {
        float acc = 0.0f;
        #pragma unroll
        for (int n = 0; n < NN_; n++) acc += s[n * F_ + tid];
        m[tid] = acc * (1.0f / 32.0f);
    }
    __syncthreads();
    float acc = gb[tid];
    #pragma unroll
    for (int f = 0; f < F_; f++) acc += m[f] * gw[f * D_ + tid];
    d_G[(size_t)row * D_ + tid] = fmaxf(acc, 0.0f);
}

// ======================================================================
// f32x2 SGEMM-NT, BM=128 BN=128 BK=16, 256 threads.
// C[M,N] = A[M,K] @ B[N,K]^T + bias[N]; flags: 1=relu, 2=permute store
// ======================================================================
__global__ void __launch_bounds__(256, 1)
sgemm128(const float* __restrict__ A, const float* __restrict__ Bm,
         const float* __restrict__ bias, float* __restrict__ C,
         int M, int N, int K, int flags) {
    __shared__ __align__(16) float As[16][128];
    __shared__ __align__(16) ull   BsD[16][128];   // duplicated pairs

    int tid = threadIdx.x;
    int m0 = blockIdx.y * 128, n0 = blockIdx.x * 128;
    int tm = (tid >> 4) * 8, tn = (tid & 15) * 8;

    ull acc[4][8];
    #pragma unroll
    for (int i = 0; i < 4; i++)
        #pragma unroll
        for (int j = 0; j < 8; j++) acc[i][j] = 0ULL;

    for (int k0 = 0; k0 < K; k0 += 16) {
        #pragma unroll
        for (int i = 0; i < 2; i++) {
            int idx = tid + i * 256;
            int r  = idx >> 2;
            int kq = (idx & 3) * 4;
            float4 va = *(const float4*)&A [(size_t)(m0 + r) * K + k0 + kq];
            As[kq + 0][r] = va.x; As[kq + 1][r] = va.y;
            As[kq + 2][r] = va.z; As[kq + 3][r] = va.w;
            float4 vb = *(const float4*)&Bm[(size_t)(n0 + r) * K + k0 + kq];
            BsD[kq + 0][r] = dup2(vb.x); BsD[kq + 1][r] = dup2(vb.y);
            BsD[kq + 2][r] = dup2(vb.z); BsD[kq + 3][r] = dup2(vb.w);
        }
        __syncthreads();
        #pragma unroll
        for (int kk = 0; kk < 16; kk++) {
            float4 a03 = *(const float4*)&As[kk][tm];
            float4 a47 = *(const float4*)&As[kk][tm + 4];
            ull ap[4] = { ((ull*)&a03)[0], ((ull*)&a03)[1],
                          ((ull*)&a47)[0], ((ull*)&a47)[1] };
            ull bq[8];
            *(float4*)&bq[0] = *(const float4*)&BsD[kk][tn + 0];
            *(float4*)&bq[2] = *(const float4*)&BsD[kk][tn + 2];
            *(float4*)&bq[4] = *(const float4*)&BsD[kk][tn + 4];
            *(float4*)&bq[6] = *(const float4*)&BsD[kk][tn + 6];
            #pragma unroll
            for (int i = 0; i < 4; i++)
                #pragma unroll
                for (int j = 0; j < 8; j++)
                    ffma2(acc[i][j], ap[i], bq[j]);
        }
        __syncthreads();
    }

    #pragma unroll
    for (int i = 0; i < 4; i++) {
        #pragma unroll
        for (int h = 0; h < 2; h++) {
            int m = m0 + tm + 2 * i + h;
            float* crow;
            if (flags & 2) { int b = m & 31, tt = m >> 5; crow = C + (size_t)(b * T_ + tt) * N; }
            else           { crow = C + (size_t)m * N; }
            #pragma unroll
            for (int j = 0; j < 8; j += 4) {
                float4 v;
                float2 u0 = *(float2*)&acc[i][j + 0];
                float2 u1 = *(float2*)&acc[i][j + 1];
                float2 u2 = *(float2*)&acc[i][j + 2];
                float2 u3 = *(float2*)&acc[i][j + 3];
                v.x = (h ? u0.y : u0.x) + bias[n0 + tn + j + 0];
                v.y = (h ? u1.y : u1.x) + bias[n0 + tn + j + 1];
                v.z = (h ? u2.y : u2.x) + bias[n0 + tn + j + 2];
                v.w = (h ? u3.y : u3.x) + bias[n0 + tn + j + 3];
                if (flags & 1) {
                    v.x = fmaxf(v.x, 0.0f); v.y = fmaxf(v.y, 0.0f);
                    v.z = fmaxf(v.z, 0.0f); v.w = fmaxf(v.w, 0.0f);
                }
                *(float4*)&crow[n0 + tn + j] = v;
            }
        }
    }
}

// ======================================================================
// f32x2 SGEMM-NT, BM=64 BN=128 BK=16, 128 threads (more blocks -> full chip)
// ======================================================================
__global__ void __launch_bounds__(128)
sgemm64(const float* __restrict__ A, const float* __restrict__ Bm,
        const float* __restrict__ bias, float* __restrict__ C,
        int M, int N, int K, int flags) {
    __shared__ __align__(16) float As[16][64];
    __shared__ __align__(16) ull   BsD[16][128];

    int tid = threadIdx.x;
    int m0 = blockIdx.y * 64, n0 = blockIdx.x * 128;
    int tm = (tid >> 4) * 8, tn = (tid & 15) * 8;

    ull acc[4][8];
    #pragma unroll
    for (int i = 0; i < 4; i++)
        #pragma unroll
        for (int j = 0; j < 8; j++) acc[i][j] = 0ULL;

    for (int k0 = 0; k0 < K; k0 += 16) {
        #pragma unroll
        for (int i = 0; i < 2; i++) {
            int idx = tid + i * 128;
            int r  = idx >> 2;
            int kq = (idx & 3) * 4;
            float4 va = *(const float4*)&A[(size_t)(m0 + r) * K + k0 + kq];
            As[kq + 0][r] = va.x; As[kq + 1][r] = va.y;
            As[kq + 2][r] = va.z; As[kq + 3][r] = va.w;
        }
        #pragma unroll
        for (int i = 0; i < 4; i++) {
            int idx = tid + i * 128;
            int r  = idx >> 2;
            int kq = (idx & 3) * 4;
            float4 vb = *(const float4*)&Bm[(size_t)(n0 + r) * K + k0 + kq];
            BsD[kq + 0][r] = dup2(vb.x); BsD[kq + 1][r] = dup2(vb.y);
            BsD[kq + 2][r] = dup2(vb.z); BsD[kq + 3][r] = dup2(vb.w);
        }
        __syncthreads();
        #pragma unroll
        for (int kk = 0; kk < 16; kk++) {
            float4 a03 = *(const float4*)&As[kk][tm];
            float4 a47 = *(const float4*)&As[kk][tm + 4];
            ull ap[4] = { ((ull*)&a03)[0], ((ull*)&a03)[1],
                          ((ull*)&a47)[0], ((ull*)&a47)[1] };
            ull bq[8];
            *(float4*)&bq[0] = *(const float4*)&BsD[kk][tn + 0];
            *(float4*)&bq[2] = *(const float4*)&BsD[kk][tn + 2];
            *(float4*)&bq[4] = *(const float4*)&BsD[kk][tn + 4];
            *(float4*)&bq[6] = *(const float4*)&BsD[kk][tn + 6];
            #pragma unroll
            for (int i = 0; i < 4; i++)
                #pragma unroll
                for (int j = 0; j < 8; j++)
                    ffma2(acc[i][j], ap[i], bq[j]);
        }
        __syncthreads();
    }

    #pragma unroll
    for (int i = 0; i < 4; i++) {
        #pragma unroll
        for (int h = 0; h < 2; h++) {
            int m = m0 + tm + 2 * i + h;
            float* crow;
            if (flags & 2) { int b = m & 31, tt = m >> 5; crow = C + (size_t)(b * T_ + tt) * N; }
            else           { crow = C + (size_t)m * N; }
            #pragma unroll
            for (int j = 0; j < 8; j += 4) {
                float4 v;
                float2 u0 = *(float2*)&acc[i][j + 0];
                float2 u1 = *(float2*)&acc[i][j + 1];
                float2 u2 = *(float2*)&acc[i][j + 2];
                float2 u3 = *(float2*)&acc[i][j + 3];
                v.x = (h ? u0.y : u0.x) + bias[n0 + tn + j + 0];
                v.y = (h ? u1.y : u1.x) + bias[n0 + tn + j + 1];
                v.z = (h ? u2.y : u2.x) + bias[n0 + tn + j + 2];
                v.w = (h ? u3.y : u3.x) + bias[n0 + tn + j + 3];
                if (flags & 1) {
                    v.x = fmaxf(v.x, 0.0f); v.y = fmaxf(v.y, 0.0f);
                    v.z = fmaxf(v.z, 0.0f); v.w = fmaxf(v.w, 0.0f);
                }
                *(float4*)&crow[n0 + tn + j] = v;
            }
        }
    }
}

// ======================================================================
// Persistent LSTM, float4 k-major h layout, FFMA2 inner loop.
// smem: ws4 32KB | h4 64KB | pacc 16KB | zbuf 2KB | cs 0.5KB
// ======================================================================
#define SM_WS4   0
#define SM_H4    (SM_WS4 + 16 * 128 * 16)
#define SM_PACC  (SM_H4  + 128 * 32 * 16)
#define SM_ZBUF  (SM_PACC + 8 * 16 * 32 * 4)
#define SM_CS    (SM_ZBUF + 16 * 32 * 4)
#define SM_TOTAL (SM_CS + 128 * 4)

__global__ void __launch_bounds__(256, 1)
k_lstm(const float* __restrict__ whh) {
    extern __shared__ char smem[];
    float4* ws4  = (float4*)(smem + SM_WS4);   // [r][q]  r=gate*4+jj, q=k/4
    float4* h4   = (float4*)(smem + SM_H4);    // [q][b]
    float*  pacc = (float*) (smem + SM_PACC);  // [w][r][b]
    float*  zbuf = (float*) (smem + SM_ZBUF);  // [r][b]
    float*  cs   = (float*) (smem + SM_CS);    // [jj][b]

    int tid = threadIdx.x, lane = tid & 31, wrp = tid >> 5;
    int j0 = blockIdx.x * 4;

    // stage w_hh slice once: 16 rows x 128 q
    #pragma unroll
    for (int i = 0; i < 8; i++) {
        int idx = i * 256 + tid;
        int r = idx >> 7, q = idx & 127;
        int rr = (r >> 2) * LH + j0 + (r & 3);
        ws4[r * 128 + q] = ((const float4*)whh)[(size_t)rr * 128 + q];
    }
    if (tid < 128) cs[tid] = 0.0f;
    __syncthreads();

    const int qbase = wrp * 16;
    // reduce-phase indices
    const int r0 = tid >> 5,        rb = tid & 31;
    const int r1 = (tid + 256) >> 5;
    const int xoff0 = (r0 >> 2) * LH + j0 + (r0 & 3);
    const int xoff1 = (r1 >> 2) * LH + j0 + (r1 & 3);

    for (int t = 0; t < T_; t++) {
        // prefetch X[t] for this thread's two reduce outputs
        float xv0 = __ldcg(&d_X[(size_t)(t * 32 + rb) * G4 + xoff0]);
        float xv1 = __ldcg(&d_X[(size_t)(t * 32 + rb) * G4 + xoff1]);

        // stage h: coalesced LDG.128 -> conflict-free STS.128
        const float4* hin = (const float4*)d_hbuf[t & 1];
        #pragma unroll
        for (int i = 0; i < 16; i++) {
            int idx = i * 256 + tid;        // == q*32 + b
            h4[idx] = __ldcg(&hin[idx]);
        }
        __syncthreads();

        // packed GEMM: warp owns q-slice [qbase, qbase+16)
        ull alo[16], ahi[16];
        #pragma unroll
        for (int r = 0; r < 16; r++) { alo[r] = 0ULL; ahi[r] = 0ULL; }
        #pragma unroll
        for (int qq = 0; qq < 16; qq++) {
            float4 hv = h4[(qbase + qq) * 32 + lane];
            ull hlo = ((ull*)&hv)[0], hhi = ((ull*)&hv)[1];
            #pragma unroll
            for (int r = 0; r < 16; r++) {
                float4 wv = ws4[r * 128 + qbase + qq];
                ffma2(alo[r], ((ull*)&wv)[0], hlo);
                ffma2(ahi[r], ((ull*)&wv)[1], hhi);
            }
        }
        #pragma unroll
        for (int r = 0; r < 16; r++) {
            float2 a = *(float2*)&alo[r], b = *(float2*)&ahi[r];
            pacc[(wrp * 16 + r) * 32 + lane] = a.x + a.y + b.x + b.y;
        }
        __syncthreads();

        // reduce 8 warps + X
        {
            float z0 = xv0, z1 = xv1;
            #pragma unroll
            for (int w = 0; w < 8; w++) {
                z0 += pacc[(w * 16 + r0) * 32 + rb];
                z1 += pacc[(w * 16 + r1) * 32 + rb];
            }
            zbuf[r0 * 32 + rb] = z0;
            zbuf[r1 * 32 + rb] = z1;
        }
        __syncthreads();

        // pointwise
        if (tid < 128) {
            int b = tid >> 2, jj = tid & 3;
            float zi = zbuf[( 0 + jj) * 32 + b];
            float zf = zbuf[( 4 + jj) * 32 + b];
            float zg = zbuf[( 8 + jj) * 32 + b];
            float zo = zbuf[(12 + jj) * 32 + b];
            float cp = cs[jj * 32 + b];
            float ig = 1.0f / (1.0f + __expf(-zi));
            float fg = 1.0f / (1.0f + __expf(-zf));
            float gg = tanhf(zg);
            float og = 1.0f / (1.0f + __expf(-zo));
            float cn = fg * cp + ig * gg;
            float hn = og * tanhf(cn);
            cs[jj * 32 + b] = cn;
            // h next: float4-grouped k-major: j = j0+jj, q = blockIdx.x
            d_hbuf[(t + 1) & 1][blockIdx.x * 128 + b * 4 + jj] = hn;
            d_L[(size_t)(t * 32 + b) * LH + j0 + jj] = hn;
        }

        // device-wide barrier
        __threadfence();
        __syncthreads();
        if (tid == 0) {
            atomicAdd(&d_bar, 1);
            volatile int* vb = &d_bar;
            while (*vb < NBLK * (t + 1)) { }
        }
        __syncthreads();
    }
}

// ======================================================================
extern "C" void kernel_launch(void* const* d_in, const int* in_sizes, int n_in,
                              void* d_out, int out_size) {
    const float* traj      = (const float*)d_in[0];
    const float* gcn_w     = (const float*)d_in[1];
    const float* gcn_b     = (const float*)d_in[2];
    const float* in_proj_w = (const float*)d_in[3];
    const float* in_proj_b = (const float*)d_in[4];
    const float* out_proj_w= (const float*)d_in[5];
    const float* out_proj_b= (const float*)d_in[6];
    // d_in[7]=va_w, d_in[8]=va_b : unused (uniform softmaxes)
    const float* w_ih      = (const float*)d_in[9];
    const float* w_hh      = (const float*)d_in[10];
    const float* b_ih      = (const float*)d_in[11];
    const float* b_hh      = (const float*)d_in[12];
    const float* lin1_w    = (const float*)d_in[13];
    const float* lin1_b    = (const float*)d_in[14];
    const float* lin2_w    = (const float*)d_in[15];
    const float* lin2_b    = (const float*)d_in[16];
    float* out = (float*)d_out;

    float *pG, *pV, *pATT, *pX, *pbihh, *pL, *pH1;
    cudaGetSymbolAddress((void**)&pG,    d_G);
    cudaGetSymbolAddress((void**)&pV,    d_V);
    cudaGetSymbolAddress((void**)&pATT,  d_ATT);
    cudaGetSymbolAddress((void**)&pX,    d_X);
    cudaGetSymbolAddress((void**)&pbihh, d_bihh);
    cudaGetSymbolAddress((void**)&pL,    d_L);
    cudaGetSymbolAddress((void**)&pH1,   d_H1);

    static int smem_set = 0;
    if (!smem_set) {
        cudaFuncSetAttribute(k_lstm, cudaFuncAttributeMaxDynamicSharedMemorySize,
                             SM_TOTAL);
        smem_set = 1;
    }

    k_zero<<<(B_ * LH + 255) / 256, 256>>>();
    k_bihh<<<(G4 + 255) / 256, 256>>>(b_ih, b_hh);
    k_G<<<ROWS, 256>>>(traj, gcn_w, gcn_b);

    // V = G @ Wv^T + bv
    sgemm64<<<dim3(D_ / 128, ROWS / 64), 128>>>(
        pG, in_proj_w + (size_t)2 * D_ * D_, in_proj_b + 2 * D_, pV,
        ROWS, D_, D_, 0);
    // ATT = V @ Wop^T + bop
    sgemm64<<<dim3(D_ / 128, ROWS / 64), 128>>>(
        pV, out_proj_w, out_proj_b, pATT, ROWS, D_, D_, 0);
    // X = ATT @ w_ih^T + (b_ih+b_hh)
    sgemm128<<<dim3(G4 / 128, ROWS / 128), 256>>>(
        pATT, w_ih, pbihh, pX, ROWS, G4, D_, 0);

    // persistent LSTM
    k_lstm<<<NBLK, 256, SM_TOTAL>>>(w_hh);

    // MLP
    sgemm64<<<dim3(D_ / 128, ROWS / 64), 128>>>(
        pL, lin1_w, lin1_b, pH1, ROWS, D_, LH, 1);
    sgemm64<<<dim3(128 / 128, ROWS / 64), 128>>>(
        pH1, lin2_w, lin2_b, out, ROWS, 128, D_, 2);
}

// round 4
// speedup vs baseline: 1.3053x; 1.3053x over previous
#include <cuda_runtime.h>
#include <math.h>

// ----- problem dims -----
#define B_    32
#define T_    100
#define NN_   32
#define F_    8
#define D_    256
#define LH    512
#define G4    2048      // 4*LH
#define ROWS  3200      // B_*T_  (row = t*32 + b)
#define NBLK  128       // persistent LSTM grid

typedef unsigned long long ull;

// ----- device scratch -----
__device__ float d_G   [ROWS * D_];
__device__ float d_F1  [G4 * D_];     // w_ih @ Wop
__device__ float d_Wbig[G4 * D_];     // w_ih @ Wop @ Wv
__device__ float d_batt[D_];          // Wop@bv + bop
__device__ float d_bihh[G4];          // w_ih@batt + b_ih + b_hh
__device__ float d_X   [ROWS * G4];
// hidden state, float4-grouped k-major: element (j,b) at (j>>2)*128 + b*4 + (j&3)
__device__ float d_hbuf[2][B_ * LH];
__device__ float d_L   [ROWS * LH];
__device__ float d_H1  [ROWS * D_];
__device__ int   d_bar;

__device__ __forceinline__ void ffma2(ull& d, ull a, ull b) {
    asm("fma.rn.f32x2 %0, %1, %2, %0;" : "+l"(d) : "l"(a), "l"(b));
}

// fast safe tanh: e = exp(-2|x|) in (0,1]; t = sign * (1-e)/(1+e)
__device__ __forceinline__ float tanh_fast(float x) {
    float ax = fabsf(x);
    float e  = __expf(-2.0f * ax);
    float t  = __fdividef(1.0f - e, 1.0f + e);
    return copysignf(t, x);
}
__device__ __forceinline__ float sigm(float x) {
    return 1.0f / (1.0f + __expf(-x));
}

// ======================================================================
__global__ void k_zero() {
    int i = blockIdx.x * blockDim.x + threadIdx.x;
    if (i < B_ * LH) d_hbuf[0][i] = 0.0f;
    if (i == 0) d_bar = 0;
}

// ======================================================================
// GEMV (warp-per-row): out[j] = dot(W[j,:K], x) + add1[j] (+ add2[j])
// ======================================================================
__global__ void k_gemv(const float* __restrict__ W, int K,
                       const float* __restrict__ x,
                       const float* __restrict__ add1,
                       const float* __restrict__ add2,
                       float* __restrict__ out, int M) {
    int gw   = (blockIdx.x * blockDim.x + threadIdx.x) >> 5;
    int lane = threadIdx.x & 31;
    if (gw >= M) return;
    float s = 0.0f;
    for (int k = lane; k < K; k += 32)
        s += W[(size_t)gw * K + k] * x[k];
    #pragma unroll
    for (int off = 16; off > 0; off >>= 1)
        s += __shfl_xor_sync(0xffffffff, s, off);
    if (lane == 0) {
        float r = s + add1[gw];
        if (add2) r += add2[gw];
        out[gw] = r;
    }
}

// ======================================================================
// G[row,d] = relu( (mean_n traj[b,t,n,:]) @ gcn_w + gcn_b )
// ======================================================================
__global__ void k_G(const float* __restrict__ traj,
                    const float* __restrict__ gw,
                    const float* __restrict__ gb) {
    int row = blockIdx.x;
    int t = row >> 5, b = row & 31;
    __shared__ float s[NN_ * F_];
    __shared__ float m[F_];
    int tid = threadIdx.x;
    const float* p = traj + (size_t)((b * T_ + t) * NN_) * F_;
    s[tid] = p[tid];
    __syncthreads();
    if (tid < F_) {
        float acc = 0.0f;
        #pragma unroll
        for (int n = 0; n < NN_; n++) acc += s[n * F_ + tid];
        m[tid] = acc * (1.0f / 32.0f);
    }
    __syncthreads();
    float acc = gb[tid];
    #pragma unroll
    for (int f = 0; f < F_; f++) acc += m[f] * gw[f * D_ + tid];
    d_G[(size_t)row * D_ + tid] = fmaxf(acc, 0.0f);
}

// ======================================================================
// SGEMM-NT (proven R1 kernel): C[M,N] = A[M,K] @ B[N,K]^T + bias[N]
// BM=BN=128, BK=16, 256 threads, 8x8 micro-tile.
// ======================================================================
__global__ void __launch_bounds__(256)
sgemm_nt(const float* __restrict__ A, const float* __restrict__ Bm,
         const float* __restrict__ bias, float* __restrict__ C,
         int M, int N, int K) {
    __shared__ __align__(16) float As[16][128];
    __shared__ __align__(16) float Bs[16][128];

    int tid = threadIdx.x;
    int m0 = blockIdx.y * 128, n0 = blockIdx.x * 128;
    int tm = (tid >> 4) * 8, tn = (tid & 15) * 8;

    float acc[8][8];
    #pragma unroll
    for (int i = 0; i < 8; i++)
        #pragma unroll
        for (int j = 0; j < 8; j++) acc[i][j] = 0.0f;

    for (int k0 = 0; k0 < K; k0 += 16) {
        #pragma unroll
        for (int i = 0; i < 2; i++) {
            int idx = tid + i * 256;
            int r  = idx >> 2;
            int kq = (idx & 3) * 4;
            float4 va = *(const float4*)&A [(size_t)(m0 + r) * K + k0 + kq];
            As[kq + 0][r] = va.x; As[kq + 1][r] = va.y;
            As[kq + 2][r] = va.z; As[kq + 3][r] = va.w;
            float4 vb = *(const float4*)&Bm[(size_t)(n0 + r) * K + k0 + kq];
            Bs[kq + 0][r] = vb.x; Bs[kq + 1][r] = vb.y;
            Bs[kq + 2][r] = vb.z; Bs[kq + 3][r] = vb.w;
        }
        __syncthreads();
        #pragma unroll
        for (int kk = 0; kk < 16; kk++) {
            float a[8], b[8];
            *(float4*)&a[0] = *(const float4*)&As[kk][tm];
            *(float4*)&a[4] = *(const float4*)&As[kk][tm + 4];
            *(float4*)&b[0] = *(const float4*)&Bs[kk][tn];
            *(float4*)&b[4] = *(const float4*)&Bs[kk][tn + 4];
            #pragma unroll
            for (int i = 0; i < 8; i++)
                #pragma unroll
                for (int j = 0; j < 8; j++)
                    acc[i][j] += a[i] * b[j];
        }
        __syncthreads();
    }

    #pragma unroll
    for (int i = 0; i < 8; i++) {
        float* crow = C + (size_t)(m0 + tm + i) * N;
        #pragma unroll
        for (int j = 0; j < 8; j += 4) {
            float4 v;
            v.x = acc[i][j + 0] + bias[n0 + tn + j + 0];
            v.y = acc[i][j + 1] + bias[n0 + tn + j + 1];
            v.z = acc[i][j + 2] + bias[n0 + tn + j + 2];
            v.w = acc[i][j + 3] + bias[n0 + tn + j + 3];
            *(float4*)&crow[n0 + tn + j] = v;
        }
    }
}

// ======================================================================
// SGEMM BM=64 BN=128 BK=16, 256 threads (2 warps/SMSP), 4x8 micro-tile.
// flags: 1=relu, 2=permute rows (t*32+b -> b*T+t), 4=NN (B is W[K,N]),
//        8=no bias
// ======================================================================
__global__ void __launch_bounds__(256)
sgemm64b(const float* __restrict__ A, const float* __restrict__ Bm,
         const float* __restrict__ bias, float* __restrict__ C,
         int M, int N, int K, int flags) {
    __shared__ __align__(16) float As[16][64];
    __shared__ __align__(16) float Bs[16][128];

    int tid = threadIdx.x;
    int m0 = blockIdx.y * 64, n0 = blockIdx.x * 128;
    int tm = (tid >> 4) * 4, tn = (tid & 15) * 8;

    float acc[4][8];
    #pragma unroll
    for (int i = 0; i < 4; i++)
        #pragma unroll
        for (int j = 0; j < 8; j++) acc[i][j] = 0.0f;

    for (int k0 = 0; k0 < K; k0 += 16) {
        {   // A tile: 64 rows x 16 k = 1024 floats, 1 float4/thread
            int r  = tid >> 2;
            int kq = (tid & 3) * 4;
            float4 va = *(const float4*)&A[(size_t)(m0 + r) * K + k0 + kq];
            As[kq + 0][r] = va.x; As[kq + 1][r] = va.y;
            As[kq + 2][r] = va.z; As[kq + 3][r] = va.w;
        }
        if (flags & 4) {   // NN: W[k][n], leading dim N
            #pragma unroll
            for (int i = 0; i < 2; i++) {
                int idx = tid + i * 256;
                int kk = idx >> 5;
                int c  = (idx & 31) * 4;
                float4 vb = *(const float4*)&Bm[(size_t)(k0 + kk) * N + n0 + c];
                *(float4*)&Bs[kk][c] = vb;
            }
        } else {           // NT: B[n][k]
            #pragma unroll
            for (int i = 0; i < 2; i++) {
                int idx = tid + i * 256;
                int r  = idx >> 2;
                int kq = (idx & 3) * 4;
                float4 vb = *(const float4*)&Bm[(size_t)(n0 + r) * K + k0 + kq];
                Bs[kq + 0][r] = vb.x; Bs[kq + 1][r] = vb.y;
                Bs[kq + 2][r] = vb.z; Bs[kq + 3][r] = vb.w;
            }
        }
        __syncthreads();
        #pragma unroll
        for (int kk = 0; kk < 16; kk++) {
            float a[4], b[8];
            *(float4*)&a[0] = *(const float4*)&As[kk][tm];
            *(float4*)&b[0] = *(const float4*)&Bs[kk][tn];
            *(float4*)&b[4] = *(const float4*)&Bs[kk][tn + 4];
            #pragma unroll
            for (int i = 0; i < 4; i++)
                #pragma unroll
                for (int j = 0; j < 8; j++)
                    acc[i][j] += a[i] * b[j];
        }
        __syncthreads();
    }

    #pragma unroll
    for (int i = 0; i < 4; i++) {
        int m = m0 + tm + i;
        float* crow;
        if (flags & 2) { int b = m & 31, tt = m >> 5; crow = C + (size_t)(b * T_ + tt) * N; }
        else           { crow = C + (size_t)m * N; }
        #pragma unroll
        for (int j = 0; j < 8; j += 4) {
            float4 v;
            v.x = acc[i][j + 0]; v.y = acc[i][j + 1];
            v.z = acc[i][j + 2]; v.w = acc[i][j + 3];
            if (!(flags & 8)) {
                v.x += bias[n0 + tn + j + 0]; v.y += bias[n0 + tn + j + 1];
                v.z += bias[n0 + tn + j + 2]; v.w += bias[n0 + tn + j + 3];
            }
            if (flags & 1) {
                v.x = fmaxf(v.x, 0.0f); v.y = fmaxf(v.y, 0.0f);
                v.z = fmaxf(v.z, 0.0f); v.w = fmaxf(v.w, 0.0f);
            }
            *(float4*)&crow[n0 + tn + j] = v;
        }
    }
}

// ======================================================================
// Persistent LSTM: 128 blocks x 256 threads; merged reduce+pointwise.
// ======================================================================
#define SM_WS4   0
#define SM_H4    (SM_WS4 + 16 * 128 * 16)
#define SM_PACC  (SM_H4  + 128 * 32 * 16)
#define SM_CS    (SM_PACC + 8 * 16 * 32 * 4)
#define SM_TOTAL (SM_CS + 128 * 4)

__global__ void __launch_bounds__(256, 1)
k_lstm(const float* __restrict__ whh) {
    extern __shared__ char smem[];
    float4* ws4  = (float4*)(smem + SM_WS4);   // [r][q]  r=gate*4+jj
    float4* h4   = (float4*)(smem + SM_H4);    // [q][b]
    float*  pacc = (float*) (smem + SM_PACC);  // [w][r][b]
    float*  cs   = (float*) (smem + SM_CS);    // [jj][b]

    int tid = threadIdx.x, lane = tid & 31, wrp = tid >> 5;
    int j0 = blockIdx.x * 4;

    // stage w_hh slice once: 16 rows x 128 q
    #pragma unroll
    for (int i = 0; i < 8; i++) {
        int idx = i * 256 + tid;
        int r = idx >> 7, q = idx & 127;
        int rr = (r >> 2) * LH + j0 + (r & 3);
        ws4[r * 128 + q] = ((const float4*)whh)[(size_t)rr * 128 + q];
    }
    if (tid < 128) cs[tid] = 0.0f;
    __syncthreads();

    const int qbase = wrp * 16;
    // pointwise mapping: warp = jj, lane = b (conflict-free pacc reads)
    const int pjj = tid >> 5;      // valid when tid < 128
    const int pb  = tid & 31;

    for (int t = 0; t < T_; t++) {
        // prefetch this thread's 4 X gate values
        float xg0 = 0, xg1 = 0, xg2 = 0, xg3 = 0;
        if (tid < 128) {
            const float* xr = d_X + (size_t)(t * 32 + pb) * G4 + j0 + pjj;
            xg0 = xr[0 * LH]; xg1 = xr[1 * LH];
            xg2 = xr[2 * LH]; xg3 = xr[3 * LH];
        }

        // stage h: coalesced LDG.128 -> STS.128
        const float4* hin = (const float4*)d_hbuf[t & 1];
        #pragma unroll
        for (int i = 0; i < 16; i++) {
            int idx = i * 256 + tid;        // == q*32 + b
            h4[idx] = __ldcg(&hin[idx]);
        }
        __syncthreads();

        // packed GEMM: warp owns q-slice [qbase, qbase+16)
        ull alo[16], ahi[16];
        #pragma unroll
        for (int r = 0; r < 16; r++) { alo[r] = 0ULL; ahi[r] = 0ULL; }
        #pragma unroll
        for (int qq = 0; qq < 16; qq++) {
            float4 hv = h4[(qbase + qq) * 32 + lane];
            ull hlo = ((ull*)&hv)[0], hhi = ((ull*)&hv)[1];
            #pragma unroll
            for (int r = 0; r < 16; r++) {
                float4 wv = ws4[r * 128 + qbase + qq];
                ffma2(alo[r], ((ull*)&wv)[0], hlo);
                ffma2(ahi[r], ((ull*)&wv)[1], hhi);
            }
        }
        #pragma unroll
        for (int r = 0; r < 16; r++) {
            float2 a = *(float2*)&alo[r], b = *(float2*)&ahi[r];
            pacc[(wrp * 16 + r) * 32 + lane] = a.x + a.y + b.x + b.y;
        }
        __syncthreads();

        // merged reduce + pointwise (tid < 128): warp=jj, lane=b
        if (tid < 128) {
            float zi = xg0, zf = xg1, zg = xg2, zo = xg3;
            #pragma unroll
            for (int w = 0; w < 8; w++) {
                const float* pw = pacc + (w * 16) * 32 + pb;
                zi += pw[( 0 + pjj) * 32];
                zf += pw[( 4 + pjj) * 32];
                zg += pw[( 8 + pjj) * 32];
                zo += pw[(12 + pjj) * 32];
            }
            float cp = cs[pjj * 32 + pb];
            float ig = sigm(zi), fg = sigm(zf);
            float gg = tanh_fast(zg), og = sigm(zo);
            float cn = fg * cp + ig * gg;
            float hn = og * tanh_fast(cn);
            cs[pjj * 32 + pb] = cn;
            d_hbuf[(t + 1) & 1][blockIdx.x * 128 + pb * 4 + pjj] = hn;
            d_L[(size_t)(t * 32 + pb) * LH + j0 + pjj] = hn;
            __threadfence();
        }

        // device-wide barrier
        __syncthreads();
        if (tid == 0) {
            atomicAdd(&d_bar, 1);
            volatile int* vb = &d_bar;
            while (*vb < NBLK * (t + 1)) { }
        }
        __syncthreads();
    }
}

// ======================================================================
extern "C" void kernel_launch(void* const* d_in, const int* in_sizes, int n_in,
                              void* d_out, int out_size) {
    const float* traj      = (const float*)d_in[0];
    const float* gcn_w     = (const float*)d_in[1];
    const float* gcn_b     = (const float*)d_in[2];
    const float* in_proj_w = (const float*)d_in[3];
    const float* in_proj_b = (const float*)d_in[4];
    const float* out_proj_w= (const float*)d_in[5];
    const float* out_proj_b= (const float*)d_in[6];
    // d_in[7]=va_w, d_in[8]=va_b : unused (uniform softmaxes)
    const float* w_ih      = (const float*)d_in[9];
    const float* w_hh      = (const float*)d_in[10];
    const float* b_ih      = (const float*)d_in[11];
    const float* b_hh      = (const float*)d_in[12];
    const float* lin1_w    = (const float*)d_in[13];
    const float* lin1_b    = (const float*)d_in[14];
    const float* lin2_w    = (const float*)d_in[15];
    const float* lin2_b    = (const float*)d_in[16];
    float* out = (float*)d_out;

    float *pG, *pF1, *pWbig, *pbatt, *pbihh, *pX, *pL, *pH1;
    cudaGetSymbolAddress((void**)&pG,    d_G);
    cudaGetSymbolAddress((void**)&pF1,   d_F1);
    cudaGetSymbolAddress((void**)&pWbig, d_Wbig);
    cudaGetSymbolAddress((void**)&pbatt, d_batt);
    cudaGetSymbolAddress((void**)&pbihh, d_bihh);
    cudaGetSymbolAddress((void**)&pX,    d_X);
    cudaGetSymbolAddress((void**)&pL,    d_L);
    cudaGetSymbolAddress((void**)&pH1,   d_H1);

    static int smem_set = 0;
    if (!smem_set) {
        cudaFuncSetAttribute(k_lstm, cudaFuncAttributeMaxDynamicSharedMemorySize,
                             SM_TOTAL);
        smem_set = 1;
    }

    const float* bv = in_proj_b + 2 * D_;

    k_zero<<<(B_ * LH + 255) / 256, 256>>>();
    k_G<<<ROWS, 256>>>(traj, gcn_w, gcn_b);

    // bias_att = Wop @ bv + bop   (256 rows, warp per row)
    k_gemv<<<32, 256>>>(out_proj_w, D_, bv, out_proj_b, nullptr, pbatt, D_);
    // bias_x = w_ih @ bias_att + b_ih + b_hh   (2048 rows)
    k_gemv<<<256, 256>>>(w_ih, D_, pbatt, b_ih, b_hh, pbihh, G4);

    // F1 = w_ih @ Wop   (NN, no bias)    [2048 x 256]
    sgemm64b<<<dim3(D_ / 128, G4 / 64), 256>>>(
        w_ih, out_proj_w, nullptr, pF1, G4, D_, D_, 4 | 8);
    // Wbig = F1 @ Wv    (NN, no bias)    Wv = in_proj_w rows [512:768)
    sgemm64b<<<dim3(D_ / 128, G4 / 64), 256>>>(
        pF1, in_proj_w + (size_t)2 * D_ * D_, nullptr, pWbig, G4, D_, D_, 4 | 8);

    // X = G @ Wbig^T + bias_x   (grid 400, proven 128x128 kernel)
    sgemm_nt<<<dim3(G4 / 128, ROWS / 128), 256>>>(
        pG, pWbig, pbihh, pX, ROWS, G4, D_);

    // persistent LSTM
    k_lstm<<<NBLK, 256, SM_TOTAL>>>(w_hh);

    // MLP
    sgemm64b<<<dim3(D_ / 128, ROWS / 64), 256>>>(
        pL, lin1_w, lin1_b, pH1, ROWS, D_, LH, 1 /*relu*/);
    sgemm64b<<<dim3(128 / 128, ROWS / 64), 256>>>(
        pH1, lin2_w, lin2_b, out, ROWS, 128, D_, 2 /*permute*/);
}

// round 5
// speedup vs baseline: 1.4041x; 1.0757x over previous
#include <cuda_runtime.h>
#include <math.h>

// ----- problem dims -----
#define B_    32
#define T_    100
#define NN_   32
#define F_    8
#define D_    256
#define LH    512
#define G4    2048      // 4*LH
#define ROWS  3200      // B_*T_  (row = t*32 + b)
#define NBLK  128       // persistent LSTM grid

typedef unsigned long long ull;

// ----- device scratch -----
__device__ float d_G   [ROWS * D_];
__device__ float d_F1  [G4 * D_];     // w_ih @ Wop
__device__ float d_Wbig[G4 * D_];     // w_ih @ Wop @ Wv
__device__ float d_batt[D_];          // Wop@bv + bop
__device__ float d_bihh[G4];          // w_ih@batt + b_ih + b_hh
__device__ float d_XT  [G4 * ROWS];   // X^T: [gate*512+j][t*32+b]
// hidden state, float4-grouped k-major: element (j,b) at (j>>2)*128 + b*4 + (j&3)
__device__ float d_hbuf[2][B_ * LH];
__device__ float d_LT  [LH * ROWS];   // L^T: [j][t*32+b]
__device__ float d_H1  [ROWS * D_];
__device__ int   d_bar;

__device__ __forceinline__ void ffma2(ull& d, ull a, ull b) {
    asm("fma.rn.f32x2 %0, %1, %2, %0;" : "+l"(d) : "l"(a), "l"(b));
}
__device__ __forceinline__ float tanh_fast(float x) {
    float ax = fabsf(x);
    float e  = __expf(-2.0f * ax);
    float t  = __fdividef(1.0f - e, 1.0f + e);
    return copysignf(t, x);
}
__device__ __forceinline__ float sigm(float x) {
    return 1.0f / (1.0f + __expf(-x));
}

// ======================================================================
__global__ void k_zero() {
    int i = blockIdx.x * blockDim.x + threadIdx.x;
    if (i < B_ * LH) d_hbuf[0][i] = 0.0f;
    if (i == 0) d_bar = 0;
}

// ======================================================================
// GEMV (warp-per-row): out[j] = dot(W[j,:K], x) + add1[j] (+ add2[j])
// ======================================================================
__global__ void k_gemv(const float* __restrict__ W, int K,
                       const float* __restrict__ x,
                       const float* __restrict__ add1,
                       const float* __restrict__ add2,
                       float* __restrict__ out, int M) {
    int gw   = (blockIdx.x * blockDim.x + threadIdx.x) >> 5;
    int lane = threadIdx.x & 31;
    if (gw >= M) return;
    float s = 0.0f;
    for (int k = lane; k < K; k += 32)
        s += W[(size_t)gw * K + k] * x[k];
    #pragma unroll
    for (int off = 16; off > 0; off >>= 1)
        s += __shfl_xor_sync(0xffffffff, s, off);
    if (lane == 0) {
        float r = s + add1[gw];
        if (add2) r += add2[gw];
        out[gw] = r;
    }
}

// ======================================================================
// G[row,d] = relu( (mean_n traj[b,t,n,:]) @ gcn_w + gcn_b )
// ======================================================================
__global__ void k_G(const float* __restrict__ traj,
                    const float* __restrict__ gw,
                    const float* __restrict__ gb) {
    int row = blockIdx.x;
    int t = row >> 5, b = row & 31;
    __shared__ float s[NN_ * F_];
    __shared__ float m[F_];
    int tid = threadIdx.x;
    const float* p = traj + (size_t)((b * T_ + t) * NN_) * F_;
    s[tid] = p[tid];
    __syncthreads();
    if (tid < F_) {
        float acc = 0.0f;
        #pragma unroll
        for (int n = 0; n < NN_; n++) acc += s[n * F_ + tid];
        m[tid] = acc * (1.0f / 32.0f);
    }
    __syncthreads();
    float acc = gb[tid];
    #pragma unroll
    for (int f = 0; f < F_; f++) acc += m[f] * gw[f * D_ + tid];
    d_G[(size_t)row * D_ + tid] = fmaxf(acc, 0.0f);
}

// ======================================================================
// SGEMM-NT (proven): C[M,N] = A[M,K] @ B[N,K]^T + biasM[m]
// BM=BN=128, BK=16, 256 threads, 8x8 micro-tile. Bias indexed by ROW m.
// ======================================================================
__global__ void __launch_bounds__(256)
sgemm_nt_bm(const float* __restrict__ A, const float* __restrict__ Bm,
            const float* __restrict__ biasM, float* __restrict__ C,
            int M, int N, int K) {
    __shared__ __align__(16) float As[16][128];
    __shared__ __align__(16) float Bs[16][128];

    int tid = threadIdx.x;
    int m0 = blockIdx.y * 128, n0 = blockIdx.x * 128;
    int tm = (tid >> 4) * 8, tn = (tid & 15) * 8;

    float acc[8][8];
    #pragma unroll
    for (int i = 0; i < 8; i++)
        #pragma unroll
        for (int j = 0; j < 8; j++) acc[i][j] = 0.0f;

    for (int k0 = 0; k0 < K; k0 += 16) {
        #pragma unroll
        for (int i = 0; i < 2; i++) {
            int idx = tid + i * 256;
            int r  = idx >> 2;
            int kq = (idx & 3) * 4;
            float4 va = *(const float4*)&A [(size_t)(m0 + r) * K + k0 + kq];
            As[kq + 0][r] = va.x; As[kq + 1][r] = va.y;
            As[kq + 2][r] = va.z; As[kq + 3][r] = va.w;
            float4 vb = *(const float4*)&Bm[(size_t)(n0 + r) * K + k0 + kq];
            Bs[kq + 0][r] = vb.x; Bs[kq + 1][r] = vb.y;
            Bs[kq + 2][r] = vb.z; Bs[kq + 3][r] = vb.w;
        }
        __syncthreads();
        #pragma unroll
        for (int kk = 0; kk < 16; kk++) {
            float a[8], b[8];
            *(float4*)&a[0] = *(const float4*)&As[kk][tm];
            *(float4*)&a[4] = *(const float4*)&As[kk][tm + 4];
            *(float4*)&b[0] = *(const float4*)&Bs[kk][tn];
            *(float4*)&b[4] = *(const float4*)&Bs[kk][tn + 4];
            #pragma unroll
            for (int i = 0; i < 8; i++)
                #pragma unroll
                for (int j = 0; j < 8; j++)
                    acc[i][j] += a[i] * b[j];
        }
        __syncthreads();
    }

    #pragma unroll
    for (int i = 0; i < 8; i++) {
        float bm = biasM[m0 + tm + i];
        float* crow = C + (size_t)(m0 + tm + i) * N;
        #pragma unroll
        for (int j = 0; j < 8; j += 4) {
            float4 v;
            v.x = acc[i][j + 0] + bm; v.y = acc[i][j + 1] + bm;
            v.z = acc[i][j + 2] + bm; v.w = acc[i][j + 3] + bm;
            *(float4*)&crow[n0 + tn + j] = v;
        }
    }
}

// ======================================================================
// SGEMM BM=64 BN=128 BK=16, 256 threads, 4x8 micro-tile.
// flags: 1=relu, 2=permute rows (t*32+b -> b*T+t), 4=NN (B is W[K,N]),
//        8=no bias, 16=TN (A is AT[K][M], leading dim ldat)
// ======================================================================
__global__ void __launch_bounds__(256)
sgemm64b(const float* __restrict__ A, const float* __restrict__ Bm,
         const float* __restrict__ bias, float* __restrict__ C,
         int M, int N, int K, int flags, int ldat) {
    __shared__ __align__(16) float As[16][64];
    __shared__ __align__(16) float Bs[16][128];

    int tid = threadIdx.x;
    int m0 = blockIdx.y * 64, n0 = blockIdx.x * 128;
    int tm = (tid >> 4) * 4, tn = (tid & 15) * 8;

    float acc[4][8];
    #pragma unroll
    for (int i = 0; i < 4; i++)
        #pragma unroll
        for (int j = 0; j < 8; j++) acc[i][j] = 0.0f;

    for (int k0 = 0; k0 < K; k0 += 16) {
        if (flags & 16) {  // TN: A is AT[k][m]
            int kk = tid >> 4;
            int c  = (tid & 15) * 4;
            float4 va = *(const float4*)&A[(size_t)(k0 + kk) * ldat + m0 + c];
            *(float4*)&As[kk][c] = va;
        } else {           // A row-major [m][k]
            int r  = tid >> 2;
            int kq = (tid & 3) * 4;
            float4 va = *(const float4*)&A[(size_t)(m0 + r) * K + k0 + kq];
            As[kq + 0][r] = va.x; As[kq + 1][r] = va.y;
            As[kq + 2][r] = va.z; As[kq + 3][r] = va.w;
        }
        if (flags & 4) {   // NN: W[k][n], leading dim N
            #pragma unroll
            for (int i = 0; i < 2; i++) {
                int idx = tid + i * 256;
                int kk = idx >> 5;
                int c  = (idx & 31) * 4;
                float4 vb = *(const float4*)&Bm[(size_t)(k0 + kk) * N + n0 + c];
                *(float4*)&Bs[kk][c] = vb;
            }
        } else {           // NT: B[n][k]
            #pragma unroll
            for (int i = 0; i < 2; i++) {
                int idx = tid + i * 256;
                int r  = idx >> 2;
                int kq = (idx & 3) * 4;
                float4 vb = *(const float4*)&Bm[(size_t)(n0 + r) * K + k0 + kq];
                Bs[kq + 0][r] = vb.x; Bs[kq + 1][r] = vb.y;
                Bs[kq + 2][r] = vb.z; Bs[kq + 3][r] = vb.w;
            }
        }
        __syncthreads();
        #pragma unroll
        for (int kk = 0; kk < 16; kk++) {
            float a[4], b[8];
            *(float4*)&a[0] = *(const float4*)&As[kk][tm];
            *(float4*)&b[0] = *(const float4*)&Bs[kk][tn];
            *(float4*)&b[4] = *(const float4*)&Bs[kk][tn + 4];
            #pragma unroll
            for (int i = 0; i < 4; i++)
                #pragma unroll
                for (int j = 0; j < 8; j++)
                    acc[i][j] += a[i] * b[j];
        }
        __syncthreads();
    }

    #pragma unroll
    for (int i = 0; i < 4; i++) {
        int m = m0 + tm + i;
        float* crow;
        if (flags & 2) { int b = m & 31, tt = m >> 5; crow = C + (size_t)(b * T_ + tt) * N; }
        else           { crow = C + (size_t)m * N; }
        #pragma unroll
        for (int j = 0; j < 8; j += 4) {
            float4 v;
            v.x = acc[i][j + 0]; v.y = acc[i][j + 1];
            v.z = acc[i][j + 2]; v.w = acc[i][j + 3];
            if (!(flags & 8)) {
                v.x += bias[n0 + tn + j + 0]; v.y += bias[n0 + tn + j + 1];
                v.z += bias[n0 + tn + j + 2]; v.w += bias[n0 + tn + j + 3];
            }
            if (flags & 1) {
                v.x = fmaxf(v.x, 0.0f); v.y = fmaxf(v.y, 0.0f);
                v.z = fmaxf(v.z, 0.0f); v.w = fmaxf(v.w, 0.0f);
            }
            *(float4*)&crow[n0 + tn + j] = v;
        }
    }
}

// ======================================================================
// Persistent LSTM: 128 blocks x 256 threads; coalesced XT read / LT write.
// ======================================================================
#define SM_WS4   0
#define SM_H4    (SM_WS4 + 16 * 128 * 16)
#define SM_PACC  (SM_H4  + 128 * 32 * 16)
#define SM_CS    (SM_PACC + 8 * 16 * 32 * 4)
#define SM_TOTAL (SM_CS + 128 * 4)

__global__ void __launch_bounds__(256, 1)
k_lstm(const float* __restrict__ whh) {
    extern __shared__ char smem[];
    float4* ws4  = (float4*)(smem + SM_WS4);   // [r][q]  r=gate*4+jj
    float4* h4   = (float4*)(smem + SM_H4);    // [q][b]
    float*  pacc = (float*) (smem + SM_PACC);  // [w][r][b]
    float*  cs   = (float*) (smem + SM_CS);    // [jj][b]

    int tid = threadIdx.x, lane = tid & 31, wrp = tid >> 5;
    int j0 = blockIdx.x * 4;

    // stage w_hh slice once
    #pragma unroll
    for (int i = 0; i < 8; i++) {
        int idx = i * 256 + tid;
        int r = idx >> 7, q = idx & 127;
        int rr = (r >> 2) * LH + j0 + (r & 3);
        ws4[r * 128 + q] = ((const float4*)whh)[(size_t)rr * 128 + q];
    }
    if (tid < 128) cs[tid] = 0.0f;
    __syncthreads();

    const int qbase = wrp * 16;
    const int pjj = tid >> 5;      // valid when tid < 128
    const int pb  = tid & 31;
    // coalesced XT base for this thread (gate stride added per gate)
    const size_t xbase = (size_t)(j0 + pjj) * ROWS + pb;
    const size_t gstr  = (size_t)LH * ROWS;

    for (int t = 0; t < T_; t++) {
        // prefetch X gates: fully coalesced (lane=b contiguous)
        float xg0 = 0, xg1 = 0, xg2 = 0, xg3 = 0;
        if (tid < 128) {
            size_t o = xbase + t * 32;
            xg0 = __ldcg(&d_XT[o + 0 * gstr]);
            xg1 = __ldcg(&d_XT[o + 1 * gstr]);
            xg2 = __ldcg(&d_XT[o + 2 * gstr]);
            xg3 = __ldcg(&d_XT[o + 3 * gstr]);
        }

        // stage h: coalesced LDG.128 -> STS.128
        const float4* hin = (const float4*)d_hbuf[t & 1];
        #pragma unroll
        for (int i = 0; i < 16; i++) {
            int idx = i * 256 + tid;        // == q*32 + b
            h4[idx] = __ldcg(&hin[idx]);
        }
        __syncthreads();

        // packed GEMM: warp owns q-slice [qbase, qbase+16)
        ull alo[16], ahi[16];
        #pragma unroll
        for (int r = 0; r < 16; r++) { alo[r] = 0ULL; ahi[r] = 0ULL; }
        #pragma unroll
        for (int qq = 0; qq < 16; qq++) {
            float4 hv = h4[(qbase + qq) * 32 + lane];
            ull hlo = ((ull*)&hv)[0], hhi = ((ull*)&hv)[1];
            #pragma unroll
            for (int r = 0; r < 16; r++) {
                float4 wv = ws4[r * 128 + qbase + qq];
                ffma2(alo[r], ((ull*)&wv)[0], hlo);
                ffma2(ahi[r], ((ull*)&wv)[1], hhi);
            }
        }
        #pragma unroll
        for (int r = 0; r < 16; r++) {
            float2 a = *(float2*)&alo[r], b = *(float2*)&ahi[r];
            pacc[(wrp * 16 + r) * 32 + lane] = a.x + a.y + b.x + b.y;
        }
        __syncthreads();

        // merged reduce + pointwise (tid < 128): warp=jj, lane=b
        if (tid < 128) {
            float zi = xg0, zf = xg1, zg = xg2, zo = xg3;
            #pragma unroll
            for (int w = 0; w < 8; w++) {
                const float* pw = pacc + (w * 16) * 32 + pb;
                zi += pw[( 0 + pjj) * 32];
                zf += pw[( 4 + pjj) * 32];
                zg += pw[( 8 + pjj) * 32];
                zo += pw[(12 + pjj) * 32];
            }
            float cp = cs[pjj * 32 + pb];
            float ig = sigm(zi), fg = sigm(zf);
            float gg = tanh_fast(zg), og = sigm(zo);
            float cn = fg * cp + ig * gg;
            float hn = og * tanh_fast(cn);
            cs[pjj * 32 + pb] = cn;
            d_hbuf[(t + 1) & 1][blockIdx.x * 128 + pb * 4 + pjj] = hn;
            // coalesced LT write (lane=b contiguous)
            d_LT[(size_t)(j0 + pjj) * ROWS + t * 32 + pb] = hn;
            __threadfence();
        }

        // device-wide barrier
        __syncthreads();
        if (tid == 0) {
            atomicAdd(&d_bar, 1);
            volatile int* vb = &d_bar;
            while (*vb < NBLK * (t + 1)) { }
        }
        __syncthreads();
    }
}

// ======================================================================
extern "C" void kernel_launch(void* const* d_in, const int* in_sizes, int n_in,
                              void* d_out, int out_size) {
    const float* traj      = (const float*)d_in[0];
    const float* gcn_w     = (const float*)d_in[1];
    const float* gcn_b     = (const float*)d_in[2];
    const float* in_proj_w = (const float*)d_in[3];
    const float* in_proj_b = (const float*)d_in[4];
    const float* out_proj_w= (const float*)d_in[5];
    const float* out_proj_b= (const float*)d_in[6];
    // d_in[7]=va_w, d_in[8]=va_b : unused (uniform softmaxes)
    const float* w_ih      = (const float*)d_in[9];
    const float* w_hh      = (const float*)d_in[10];
    const float* b_ih      = (const float*)d_in[11];
    const float* b_hh      = (const float*)d_in[12];
    const float* lin1_w    = (const float*)d_in[13];
    const float* lin1_b    = (const float*)d_in[14];
    const float* lin2_w    = (const float*)d_in[15];
    const float* lin2_b    = (const float*)d_in[16];
    float* out = (float*)d_out;

    float *pG, *pF1, *pWbig, *pbatt, *pbihh, *pXT, *pLT, *pH1;
    cudaGetSymbolAddress((void**)&pG,    d_G);
    cudaGetSymbolAddress((void**)&pF1,   d_F1);
    cudaGetSymbolAddress((void**)&pWbig, d_Wbig);
    cudaGetSymbolAddress((void**)&pbatt, d_batt);
    cudaGetSymbolAddress((void**)&pbihh, d_bihh);
    cudaGetSymbolAddress((void**)&pXT,   d_XT);
    cudaGetSymbolAddress((void**)&pLT,   d_LT);
    cudaGetSymbolAddress((void**)&pH1,   d_H1);

    static int smem_set = 0;
    if (!smem_set) {
        cudaFuncSetAttribute(k_lstm, cudaFuncAttributeMaxDynamicSharedMemorySize,
                             SM_TOTAL);
        smem_set = 1;
    }

    const float* bv = in_proj_b + 2 * D_;

    k_zero<<<(B_ * LH + 255) / 256, 256>>>();
    k_G<<<ROWS, 256>>>(traj, gcn_w, gcn_b);

    // bias_att = Wop @ bv + bop
    k_gemv<<<32, 256>>>(out_proj_w, D_, bv, out_proj_b, nullptr, pbatt, D_);
    // bias_x = w_ih @ bias_att + b_ih + b_hh
    k_gemv<<<256, 256>>>(w_ih, D_, pbatt, b_ih, b_hh, pbihh, G4);

    // F1 = w_ih @ Wop   (NN, no bias)
    sgemm64b<<<dim3(D_ / 128, G4 / 64), 256>>>(
        w_ih, out_proj_w, nullptr, pF1, G4, D_, D_, 4 | 8, 0);
    // Wbig = F1 @ Wv    (NN, no bias)
    sgemm64b<<<dim3(D_ / 128, G4 / 64), 256>>>(
        pF1, in_proj_w + (size_t)2 * D_ * D_, nullptr, pWbig, G4, D_, D_, 4 | 8, 0);

    // XT = Wbig @ G^T + bias_x[m]   (M=2048, N=3200, K=256)
    sgemm_nt_bm<<<dim3(ROWS / 128, G4 / 128), 256>>>(
        pWbig, pG, pbihh, pXT, G4, ROWS, D_);

    // persistent LSTM (writes LT)
    k_lstm<<<NBLK, 256, SM_TOTAL>>>(w_hh);

    // H1 = relu(L @ lin1_w^T + b)  via TN: A = LT[k][m], ldat=3200
    sgemm64b<<<dim3(D_ / 128, ROWS / 64), 256>>>(
        pLT, lin1_w, lin1_b, pH1, ROWS, D_, LH, 1 | 16, ROWS);

    // out = H1 @ lin2_w^T + b, permuted store
    sgemm64b<<<dim3(128 / 128, ROWS / 64), 256>>>(
        pH1, lin2_w, lin2_b, out, ROWS, 128, D_, 2, 0);
}